// round 12
// baseline (speedup 1.0000x reference)
#include <cuda_runtime.h>
#include <cuda_bf16.h>

// CBOW negative-sampling loss — single fused kernel.
// Inputs (metadata order):
//   d_in[0] i_emb        float32  (VOCAB+1, 50)
//   d_in[1] o_emb        float32  (VOCAB+1, 50)
//   d_in[2] target_wids  int32    (B,)
//   d_in[3] context_wids int32    (B, 10)
//   d_in[4] neg_wids     int32    (B, 10)
// Output: scalar float32 = -( sum log_sigmoid(pos) + sum log_sigmoid(-neg) )
//
// One warp per row, 128-thread blocks. Lanes 0..24 load one float2 per row
// gather (rows are 200 B, 8B-aligned). 32-bit index math. Pairwise score
// reduction (5 shfls / 2 scores). Single launch via last-block ticket.
//
// o_emb (40 MB, 11/21 of gather traffic) is loaded with an L2 evict_last
// cache policy (createpolicy + ld.global.nc.L2::cache_hint — the form ptxas
// accepts at v2.f32 width) so one full table stays L2-resident across graph
// replays; i_emb keeps default policy. Targets the measured ~48 MB/launch
// DRAM traffic (60% L2 miss) that pinned previous variants at ~18.5 us.

#define DIM2 25    // 50 floats = 25 float2
#define CTX  10
#define NNEG 10
#define MAX_BLOCKS 8192

__device__ float        g_partials[MAX_BLOCKS];
__device__ unsigned int g_count = 0;   // module-load init; reset by last block

__device__ __forceinline__ float log_sigmoid(float x) {
    // min(x,0) - log(1 + exp(-|x|)); log arg in (1,2] -> __logf is safe
    return fminf(x, 0.0f) - __logf(1.0f + __expf(-fabsf(x)));
}

// L2 evict-last access policy (keep o_emb resident).
__device__ __forceinline__ unsigned long long make_keep_policy() {
    unsigned long long pol;
    asm("createpolicy.fractional.L2::evict_last.b64 %0, 1.0;" : "=l"(pol));
    return pol;
}

// Read-only global float2 load with L2 cache-hint policy.
__device__ __forceinline__ float2 ldg_keep(const float2* p, unsigned long long pol) {
    float2 r;
    asm("ld.global.nc.L2::cache_hint.v2.f32 {%0,%1}, [%2], %3;"
        : "=f"(r.x), "=f"(r.y) : "l"(p), "l"(pol));
    return r;
}

// Reduce two independent per-lane partials A,B across the warp in 5 shfls.
// Post: lane 0 holds full sum of A; lane 16 holds full sum of B.
__device__ __forceinline__ float pair_reduce(float A, float B, int lane) {
    float x = (lane & 16) ? A : B;
    float y = __shfl_xor_sync(0xFFFFFFFFu, x, 16);
    float v = ((lane & 16) ? B : A) + y;
    v += __shfl_xor_sync(0xFFFFFFFFu, v, 8);
    v += __shfl_xor_sync(0xFFFFFFFFu, v, 4);
    v += __shfl_xor_sync(0xFFFFFFFFu, v, 2);
    v += __shfl_xor_sync(0xFFFFFFFFu, v, 1);
    return v;
}

__global__ void __launch_bounds__(128) cbow_fused_kernel(
    const float* __restrict__ i_emb,
    const float* __restrict__ o_emb,
    const int*   __restrict__ target_wids,
    const int*   __restrict__ context_wids,
    const int*   __restrict__ neg_wids,
    float*       __restrict__ out,
    int B)
{
    const int warp_global = (blockIdx.x * blockDim.x + threadIdx.x) >> 5;
    const int lane        = threadIdx.x & 31;
    const int warp_local  = threadIdx.x >> 5;

    __shared__ float  s_partial[4];
    __shared__ int    s_is_last;
    __shared__ double s_d[4];

    float loss = 0.0f;   // meaningful only on lanes 0 and 16 until combined

    if (warp_global < B) {
        const float2* __restrict__ i2 = (const float2*)i_emb;
        const float2* __restrict__ o2 = (const float2*)o_emb;
        const int*    __restrict__ cw = context_wids + warp_global * CTX;
        const int*    __restrict__ nw = neg_wids     + warp_global * NNEG;

        // ---- 32-bit row offsets (max 200001*25 = 5000025 < 2^31) ----
        int cb[CTX], nb[NNEG], tb;
        #pragma unroll
        for (int c = 0; c < CTX; c++)  cb[c] = __ldg(&cw[c]) * DIM2;
        tb = __ldg(&target_wids[warp_global]) * DIM2;
        #pragma unroll
        for (int n = 0; n < NNEG; n++) nb[n] = __ldg(&nw[n]) * DIM2;

        float ax = 0.0f, ay = 0.0f;
        float p[NNEG + 1];
        #pragma unroll
        for (int k = 0; k <= NNEG; k++) p[k] = 0.0f;

        if (lane < DIM2) {
            const unsigned long long keep = make_keep_policy();

            // ---- sum of context embeddings (default L2 policy) ----
            #pragma unroll
            for (int c = 0; c < CTX; c++) {
                const float2 e = __ldg(&i2[cb[c] + lane]);
                ax += e.x;  ay += e.y;
            }
            // ---- 11 per-lane score partials (o_emb pinned via evict_last)
            {
                const float2 e = ldg_keep(&o2[tb + lane], keep);
                p[0] = e.x * ax + e.y * ay;
            }
            #pragma unroll
            for (int n = 0; n < NNEG; n++) {
                const float2 e = ldg_keep(&o2[nb[n] + lane], keep);
                p[n + 1] = e.x * ax + e.y * ay;
            }
        }

        const float inv_ctx = 1.0f / CTX;

        // pair 0: (pos, neg0) — mixed signs
        {
            float v = pair_reduce(p[0], p[1], lane);
            if ((lane & 15) == 0) {
                float sc = v * inv_ctx;
                loss += log_sigmoid((lane & 16) ? -sc : sc);
            }
        }
        // pairs (neg1,neg2) (neg3,neg4) (neg5,neg6) (neg7,neg8)
        #pragma unroll
        for (int k = 2; k <= 8; k += 2) {
            float v = pair_reduce(p[k], p[k + 1], lane);
            if ((lane & 15) == 0)
                loss += log_sigmoid(-v * inv_ctx);
        }
        // leftover neg9: plain butterfly, accumulate at lane 0 only
        {
            float v = p[10];
            #pragma unroll
            for (int o = 16; o > 0; o >>= 1)
                v += __shfl_xor_sync(0xFFFFFFFFu, v, o);
            if (lane == 0)
                loss += log_sigmoid(-v * inv_ctx);
        }
    }

    // combine lanes 0 and 16
    loss += __shfl_xor_sync(0xFFFFFFFFu, loss, 16);
    if (lane == 0) s_partial[warp_local] = loss;
    __syncthreads();

    // block partial + last-block ticket
    if (threadIdx.x == 0) {
        float blk = s_partial[0] + s_partial[1] + s_partial[2] + s_partial[3];
        g_partials[blockIdx.x] = blk;
        __threadfence();
        unsigned int old = atomicAdd(&g_count, 1u);
        s_is_last = (old == gridDim.x - 1);
    }
    __syncthreads();

    if (s_is_last) {
        const int nb2 = gridDim.x;
        volatile float* vp = g_partials;   // writers fenced before the ticket
        double acc = 0.0;
        for (int i = threadIdx.x; i < nb2; i += 128)
            acc += (double)vp[i];
        #pragma unroll
        for (int o = 16; o > 0; o >>= 1)
            acc += __shfl_xor_sync(0xFFFFFFFFu, acc, o);
        if ((threadIdx.x & 31) == 0) s_d[threadIdx.x >> 5] = acc;
        __syncthreads();
        if (threadIdx.x == 0) {
            out[0] = (float)(-(s_d[0] + s_d[1] + s_d[2] + s_d[3]));
            g_count = 0;   // reset for next graph replay
        }
    }
}

extern "C" void kernel_launch(void* const* d_in, const int* in_sizes, int n_in,
                              void* d_out, int out_size)
{
    const float* i_emb        = (const float*)d_in[0];
    const float* o_emb        = (const float*)d_in[1];
    const int*   target_wids  = (const int*)d_in[2];
    const int*   context_wids = (const int*)d_in[3];
    const int*   neg_wids     = (const int*)d_in[4];
    float*       out          = (float*)d_out;

    const int B = in_sizes[2];
    const int warps_per_block = 128 / 32;   // 4
    int blocks = (B + warps_per_block - 1) / warps_per_block;
    if (blocks > MAX_BLOCKS) blocks = MAX_BLOCKS;   // B=16384 -> 4096 blocks

    cbow_fused_kernel<<<blocks, 128>>>(i_emb, o_emb, target_wids,
                                       context_wids, neg_wids, out, B);
}